// round 13
// baseline (speedup 1.0000x reference)
#include <cuda_runtime.h>

// R2Ntab: out[b] = (# rules r with h[b,r] > 0.999999) * [w_or>0] + b_or,
// h[b,r] = x_b . rw_r + b_and[r] - relu(rw_r).sum(), rw = w_and masked by
// w_cancel<0 columns. x binary {0,1} => pass <=> deficit(sum |w| over
// mismatched care features) < eps_r = b_and[r]-0.999999 => 256-bit pattern
// match (x_bits & care_r) == pos_r when all care weights have |w| >= eps.
//
// R13: word w = features [32w,32w+32); per-warp screening word g = gw&7
// (DRAM channel spread). NEW: Bloom screen. For full-care rules, word-g
// survival is xw == pos_g[r] exactly -> membership in an 8192-bit table:
// per row the screen is AND + LDS + bit-test (warp-uniform, no REDUX).
// False positives -> 4-rule exact screen; real survivors -> full 8-word
// check. Warps whose word g has any non-full-care rule (ncheck[g]>0,
// expected never) use the per-rule screen instead. Exact-flagged rules
// force the full path via nx. Unconditionally correct for any data.

#define FDIM 256
#define RDIM 128
#define UNROLL 16
#define NTHREADS 256
#define NBLOCKS 740
#define FULLM 0xffffffffu
#define BLOOM_BITS 8192
#define BLOOM_WORDS (BLOOM_BITS / 32)      // 256
#define BLOOM_MASK (BLOOM_BITS - 1)

__device__ unsigned g_pos[8][RDIM];
__device__ unsigned g_care[8][RDIM];
__device__ float    g_thresh[RDIM];
__device__ float    g_rw[RDIM * FDIM];
__device__ int      g_exact_flag[RDIM];
__device__ unsigned g_bloom[8][BLOOM_WORDS];
__device__ int      g_ncheck[8];

// ---------------------------------------------------------------------------
// Prep: single block, 32 warps, 4 rules each. Builds masks + Bloom tables.
// ---------------------------------------------------------------------------
__global__ void prep_kernel(const float* __restrict__ wc,
                            const float* __restrict__ wa,
                            const float* __restrict__ ba,
                            const float* __restrict__ wo) {
    __shared__ unsigned sb[8][BLOOM_WORDS];
    __shared__ int snc[8];

    const int tid  = threadIdx.x;
    const int wid  = tid >> 5;
    const int lane = tid & 31;

    for (int i = tid; i < 8 * BLOOM_WORDS; i += blockDim.x)
        (&sb[0][0])[i] = 0u;
    if (tid < 8) snc[tid] = 0;
    __syncthreads();

    for (int i = 0; i < 4; i++) {
        int r = wid + 32 * i;

        float eps     = ba[r] - 0.999999f;
        bool  include = wo[r] > 0.0f;

        float relu_sum = 0.f, sum_tiny = 0.f;
        unsigned pos[8], care[8];
#pragma unroll
        for (int w = 0; w < 8; w++) {
            int   f  = 32 * w + lane;
            float wv = (wc[f] < 0.f) ? 0.f : wa[r * FDIM + f];
            g_rw[r * FDIM + f] = wv;
            relu_sum += fmaxf(wv, 0.f);
            float aw   = fabsf(wv);
            bool  must = (aw >= eps);
            if (!must) sum_tiny += aw;
            pos[w]  = __ballot_sync(FULLM, must && (wv > 0.f));
            care[w] = __ballot_sync(FULLM, must && (wv != 0.f));
        }
#pragma unroll
        for (int o = 16; o; o >>= 1) {
            relu_sum += __shfl_xor_sync(FULLM, relu_sum, o);
            sum_tiny += __shfl_xor_sync(FULLM, sum_tiny, o);
        }

        bool afalse = (!include) || (eps <= 0.f);
        bool exact  = (!afalse) && (sum_tiny >= eps);
        if (afalse || exact) {
            // Impossible at EVERY word for the per-rule screen/full check.
#pragma unroll
            for (int w = 0; w < 8; w++) { pos[w] = 0xFFFFFFFFu; care[w] = 0u; }
        }
        if (lane == 0) {
            g_thresh[r]     = relu_sum - eps;
            g_exact_flag[r] = exact ? 1 : 0;
#pragma unroll
            for (int w = 0; w < 8; w++) { g_pos[w][r] = pos[w]; g_care[w][r] = care[w]; }
            if (!afalse && !exact) {
#pragma unroll
                for (int w = 0; w < 8; w++) {
                    if (care[w] == 0xFFFFFFFFu) {
                        unsigned h = pos[w] & BLOOM_MASK;
                        atomicOr(&sb[w][h >> 5], 1u << (h & 31));
                    } else {
                        atomicAdd(&snc[w], 1);   // can't screen by equality
                    }
                }
            }
        }
    }
    __syncthreads();

    for (int i = tid; i < 8 * BLOOM_WORDS; i += blockDim.x)
        (&g_bloom[0][0])[i] = (&sb[0][0])[i];
    if (tid < 8) g_ncheck[tid] = snc[tid];
}

// ---------------------------------------------------------------------------
// Main: warp per row, screening word g = gw&7. Fast path per row:
// 1 LDG.32/lane + 1 ballot + Bloom test (AND/LDS/bit). Uniform row mask.
// ---------------------------------------------------------------------------
__global__ void __launch_bounds__(NTHREADS, 5)
main_kernel(const float* __restrict__ x,
            const float* __restrict__ bor,
            float* __restrict__ out, int B) {
    __shared__ unsigned s_pos[8][RDIM];
    __shared__ unsigned s_care[8][RDIM];
    __shared__ unsigned s_bloom[BLOOM_WORDS];
    __shared__ int s_nx;
    __shared__ int s_xr[RDIM];

    const int tid = threadIdx.x;
    if (tid == 0) s_nx = 0;
    __syncthreads();
    for (int i = tid; i < 8 * RDIM; i += NTHREADS) {
        (&s_pos[0][0])[i]  = (&g_pos[0][0])[i];
        (&s_care[0][0])[i] = (&g_care[0][0])[i];
    }
    const int gw = blockIdx.x * (NTHREADS >> 5) + (tid >> 5);
    const int nw = gridDim.x * (NTHREADS >> 5);
    const int g  = gw & 7;                 // this warp's screening word
    // NOTE: every warp in a block has the same (tid>>5)&7 pattern; g varies
    // across the block's 8 warps since blockIdx*8 keeps all residues.
    for (int i = tid; i < BLOOM_WORDS; i += NTHREADS)
        s_bloom[i] = g_bloom[(tid & 0) + 0][i];   // placeholder overwritten below
    __syncthreads();
    // Each warp needs ITS OWN g's table; 8 warps/block cover g=0..7 exactly
    // once (gw = blockIdx*8 + wid, so g = (blockIdx*8+wid)&7 = wid&7 = wid).
    // Load warp-specific table region cooperatively: warp w loads g_bloom[w].
    {
        int wid = tid >> 5, lane = tid & 31;
        for (int i = lane; i < BLOOM_WORDS; i += 32)
            s_bloom[i] = g_bloom[wid][i];          // all warps same? NO: fix below
    }
    __syncthreads();

    // --- correction: warps share one s_bloom array, but each warp needs its
    // own table. Since g == wid for every block (gw = blockIdx*8 + wid and
    // 8 | nw), warp wid uses g_bloom[wid]; tables differ per warp, so keep
    // them in SEPARATE shared slices: s_bloom is indexed per warp below via
    // registers instead. To stay simple and correct, each warp keeps its
    // table in registers: 256 words / 32 lanes = 8 words per lane.
    unsigned bl[8];
    {
        int lane = tid & 31;
#pragma unroll
        for (int j = 0; j < 8; j++)
            bl[j] = g_bloom[g][lane + 32 * j];     // lane l holds words l,l+32,...
    }

    if (tid < RDIM && g_exact_flag[tid]) {
        int i = atomicAdd(&s_nx, 1);
        s_xr[i] = tid;
    }
    __syncthreads();

    const int   lane = tid & 31;
    const int   nx   = s_nx;
    const float b0   = bor[0];
    const int   ncheckg = g_ncheck[g];

    // Screening-word per-rule masks (second level / fallback), registers.
    unsigned pg[4], cg[4];
#pragma unroll
    for (int k = 0; k < 4; k++) {
        pg[k] = s_pos[g][lane + 32 * k];
        cg[k] = s_care[g][lane + 32 * k];
    }

    const int nchunks = B / UNROLL;

    // Full (rare) evaluation of one row: read all 8 words, full check.
    auto full_row = [&](int row) {
        unsigned xw[8];
#pragma unroll
        for (int w = 0; w < 8; w++) {
            float v = x[(size_t)row * FDIM + 32 * w + lane];
            xw[w] = __ballot_sync(FULLM, v > 0.5f);
        }
        int cnt = 0;
#pragma unroll
        for (int k = 0; k < 4; k++) {
            int r = lane + 32 * k;
            unsigned acc = 0u;
#pragma unroll
            for (int w = 0; w < 8; w++)
                acc |= (xw[w] & s_care[w][r]) ^ s_pos[w][r];
            if (acc == 0u) cnt++;
        }
        for (int e = 0; e < nx; e++) {             // exact fp32 fallback
            int r = s_xr[e];
            float s = 0.f;
#pragma unroll
            for (int w = 0; w < 8; w++) {
                if ((xw[w] >> lane) & 1u)
                    s += g_rw[r * FDIM + 32 * w + lane];
            }
#pragma unroll
            for (int o = 16; o; o >>= 1)
                s += __shfl_xor_sync(FULLM, s, o);
            if (lane == 0 && s > g_thresh[r]) cnt++;
        }
#pragma unroll
        for (int o = 16; o; o >>= 1)
            cnt += __shfl_xor_sync(FULLM, cnt, o);
        if (lane == 0) out[row] = (float)cnt + b0;
    };

    // Bloom membership test of a (warp-uniform) word value via shuffle:
    // word index h>>5 lives on lane (h>>5)&31, register j = (h>>5)>>5.
    auto bloom_hit = [&](unsigned xw) -> bool {
        unsigned h  = xw & BLOOM_MASK;             // 13 bits
        unsigned wi = h >> 5;                      // word index 0..255
        unsigned bword = __shfl_sync(FULLM, bl[wi >> 5], wi & 31);
        return (bword >> (h & 31)) & 1u;
    };

    for (int ch = gw; ch < nchunks; ch += nw) {
        int row0 = ch * UNROLL;

        // 16 independent LDG.32: 128B at offset 128*g of each of 16 rows.
        float v[UNROLL];
#pragma unroll
        for (int u = 0; u < UNROLL; u++)
            v[u] = x[(size_t)(row0 + u) * FDIM + 32 * g + lane];

        unsigned xwg[UNROLL];
#pragma unroll
        for (int u = 0; u < UNROLL; u++)
            xwg[u] = __ballot_sync(FULLM, v[u] > 0.5f);

        unsigned m = 0u;                           // warp-uniform row mask
        if (ncheckg == 0) {
#pragma unroll
            for (int u = 0; u < UNROLL; u++)
                m |= ((unsigned)bloom_hit(xwg[u])) << u;
        } else {
            // Fallback per-rule screen (expected never taken).
            unsigned candm = 0u;
#pragma unroll
            for (int u = 0; u < UNROLL; u++) {
                bool cand = false;
#pragma unroll
                for (int k = 0; k < 4; k++)
                    cand |= (((xwg[u] & cg[k]) ^ pg[k]) == 0u);
                candm |= ((unsigned)cand) << u;
            }
            m = __reduce_or_sync(FULLM, candm);
        }
        if (nx) m = (1u << UNROLL) - 1u;           // exact rules: all full

        // Coalesced store for all rejected rows (the ~always case).
        if (lane < UNROLL && !((m >> lane) & 1u))
            out[row0 + lane] = b0;

        if (m) {                                   // warp-uniform, rare
#pragma unroll
            for (int u = 0; u < UNROLL; u++) {
                if (!((m >> u) & 1u)) continue;
                // Second level: exact per-rule screen on word g.
                bool c = false;
#pragma unroll
                for (int k = 0; k < 4; k++)
                    c |= (((xwg[u] & cg[k]) ^ pg[k]) == 0u);
                unsigned any = __ballot_sync(FULLM, c);
                if (any || nx) full_row(row0 + u);          // real candidate
                else if (lane == 0) out[row0 + u] = b0;     // Bloom fp
            }
        }
    }

    // Tail rows (B not divisible by UNROLL; not hit for B = 131072).
    for (int row = nchunks * UNROLL + gw; row < B; row += nw)
        full_row(row);
}

extern "C" void kernel_launch(void* const* d_in, const int* in_sizes, int n_in,
                              void* d_out, int out_size) {
    const float* x  = (const float*)d_in[0];   // [B, 256] binary
    const float* wc = (const float*)d_in[1];   // [256]
    const float* wa = (const float*)d_in[2];   // [128, 256]
    const float* ba = (const float*)d_in[3];   // [128]
    const float* wo = (const float*)d_in[4];   // [1, 128]
    const float* bo = (const float*)d_in[5];   // [1]
    float* out = (float*)d_out;

    int B = in_sizes[0] / FDIM;

    prep_kernel<<<1, 1024>>>(wc, wa, ba, wo);      // 32 warps, 4 rules each
    main_kernel<<<NBLOCKS, NTHREADS>>>(x, bo, out, B);
}